// round 1
// baseline (speedup 1.0000x reference)
#include <cuda_runtime.h>
#include <cuda_bf16.h>

#define HH 320
#define WW 320
#define KS 31
#define PADK 15
#define HOUT 289        // 320 - 16 - 15
#define TILE 16
#define SMH 46          // TILE + KS - 1
#define SMW 48          // padded stride (conflict-free: 48 mod 32 = 16)

// Scratch for global min/max (monotonic-uint encoded floats).
__device__ unsigned g_mm[2];

__device__ __forceinline__ unsigned encf(float f) {
    unsigned u = __float_as_uint(f);
    return (u & 0x80000000u) ? ~u : (u | 0x80000000u);
}
__device__ __forceinline__ float decf(unsigned u) {
    return (u & 0x80000000u) ? __uint_as_float(u ^ 0x80000000u)
                             : __uint_as_float(~u);
}

__global__ void k_init() {
    g_mm[0] = 0xFFFFFFFFu;  // min identity (encoded)
    g_mm[1] = 0u;           // max identity (encoded)
}

__global__ __launch_bounds__(256) void k_gabor(
    const float* __restrict__ fp,
    const int*   __restrict__ fmap,
    const int*   __restrict__ tmap,
    float* __restrict__ out)
{
    __shared__ float sm[SMH * SMW];
    __shared__ unsigned swmin[8], swmax[8];

    const int tx = threadIdx.x, ty = threadIdx.y;
    const int tid = ty * TILE + tx;
    const int ox0 = blockIdx.x * TILE, oy0 = blockIdx.y * TILE;

    // Load (TILE+30)x(TILE+30) input tile; window for output (h,w) starts at (h,w).
    for (int i = tid; i < SMH * SMH; i += 256) {
        int r = i / SMH, c = i % SMH;
        int iy = oy0 + r, ix = ox0 + c;
        sm[r * SMW + c] = (iy < HH && ix < WW) ? fp[iy * WW + ix] : 0.0f;
    }
    __syncthreads();

    const int ox = ox0 + tx, oy = oy0 + ty;
    const bool valid = (ox < HOUT) && (oy < HOUT);

    float acc = 0.0f;
    if (valid) {
        const int ci = (oy + PADK) * WW + (ox + PADK);
        float th = (float)tmap[ci] / 180.0f * 3.14159265358979323846f;
        float f0 = fmaf(0.0015f, (float)fmap[ci], 0.025f);
        float st, ct;
        sincosf(th, &st, &ct);
        const float f45 = f0 * (1.0f / 45.0f);   // f0/3 * 1/half
        const float* sp = &sm[ty * SMW + tx];

        for (int a = 0; a < KS; ++a) {
            const float y = (float)(a - PADK);
            const float yct = y * ct;
            const float yst = y * st;
            const float* row = sp + a * SMW;
            #pragma unroll
            for (int b = 0; b < KS; ++b) {
                const float x  = (float)(b - PADK);
                const float xt = fmaf(x, ct, yst);      //  x*ct + y*st
                const float yt = fmaf(-x, st, yct);     // -x*st + y*ct
                const float ga = fmaf(0.04f, fabsf(yt), 1.0f);   // 1 + 0.6|yt|/15
                const float gy = ga * yt;
                const float q  = fmaf(gy, gy, xt * xt);
                const float env = expf(q * (-1.0f / 72.0f));     // 2*sigma^2 = 72
                const float fl  = fmaf(f45, yt, f0);             // chirped freq
                const float w   = env * cosf(6.283185307179586f * fl * xt);
                acc = fmaf(row[b], w, acc);
            }
        }
        out[ci] = acc;
    }

    // Block min/max over computed vals (invalid lanes carry identities).
    unsigned km = valid ? encf(acc) : 0xFFFFFFFFu;
    unsigned kM = valid ? encf(acc) : 0u;
    km = __reduce_min_sync(0xFFFFFFFFu, km);
    kM = __reduce_max_sync(0xFFFFFFFFu, kM);
    const int lane = tid & 31, wid = tid >> 5;
    if (lane == 0) { swmin[wid] = km; swmax[wid] = kM; }
    __syncthreads();
    if (tid == 0) {
        unsigned m = 0xFFFFFFFFu, M = 0u;
        #pragma unroll
        for (int i = 0; i < 8; ++i) { m = min(m, swmin[i]); M = max(M, swmax[i]); }
        atomicMin(&g_mm[0], m);
        atomicMax(&g_mm[1], M);
    }
}

__global__ __launch_bounds__(256) void k_border(
    const float* __restrict__ fp, float* __restrict__ out)
{
    __shared__ unsigned swmin[8], swmax[8];
    const int idx = blockIdx.x * 256 + threadIdx.x;
    const int i = idx / WW, j = idx % WW;
    const bool border = (i < PADK) || (i >= PADK + HOUT) ||
                        (j < PADK) || (j >= PADK + HOUT);
    unsigned km = 0xFFFFFFFFu, kM = 0u;
    if (idx < HH * WW && border) {
        float v = fp[idx];
        out[idx] = v;
        km = kM = encf(v);
    }
    km = __reduce_min_sync(0xFFFFFFFFu, km);
    kM = __reduce_max_sync(0xFFFFFFFFu, kM);
    const int lane = threadIdx.x & 31, wid = threadIdx.x >> 5;
    if (lane == 0) { swmin[wid] = km; swmax[wid] = kM; }
    __syncthreads();
    if (threadIdx.x == 0) {
        unsigned m = 0xFFFFFFFFu, M = 0u;
        #pragma unroll
        for (int i2 = 0; i2 < 8; ++i2) { m = min(m, swmin[i2]); M = max(M, swmax[i2]); }
        atomicMin(&g_mm[0], m);
        atomicMax(&g_mm[1], M);
    }
}

__global__ __launch_bounds__(256) void k_thresh(float* __restrict__ out)
{
    const int idx = blockIdx.x * 256 + threadIdx.x;
    if (idx >= HH * WW) return;
    const float mn  = decf(g_mm[0]);
    const float mxv = decf(g_mm[1]) - mn;   // max of (out - min)
    float v = out[idx] - mn;
    float t = (mxv != 0.0f) ? (v / mxv * 100.0f) : v;
    out[idx] = (t > 55.0f) ? 100.0f : 0.0f;
}

extern "C" void kernel_launch(void* const* d_in, const int* in_sizes, int n_in,
                              void* d_out, int out_size)
{
    const float* fp   = (const float*)d_in[0];   // fprint
    const int*   fmap = (const int*)d_in[1];     // freq_map
    const int*   tmap = (const int*)d_in[2];     // theta_map
    float* out = (float*)d_out;

    k_init<<<1, 1>>>();
    dim3 grid((HOUT + TILE - 1) / TILE, (HOUT + TILE - 1) / TILE);
    dim3 block(TILE, TILE);
    k_gabor<<<grid, block>>>(fp, fmap, tmap, out);
    k_border<<<(HH * WW + 255) / 256, 256>>>(fp, out);
    k_thresh<<<(HH * WW + 255) / 256, 256>>>(out);
}

// round 2
// speedup vs baseline: 3.7285x; 3.7285x over previous
#include <cuda_runtime.h>
#include <cuda_bf16.h>

#define HH 320
#define WW 320
#define KS 31
#define PADK 15
#define HOUT 289        // 320 - 16 - 15
#define NCOMBO 3600     // 180 thetas x 20 freqs
#define KROW 32         // padded kernel row (31 + 1 zero)
#define KSTRIDE (KS * KROW)   // 992 floats per combo, 3968B = 31 x 128B lines

#define PXB 8           // pixels per block (one warp per pixel)
#define SMR KS          // smem rows 31
#define SMC 40          // smem cols (38 used, padded)

// Precomputed Gabor kernel table: [3600][31*32] floats = 14.27 MB (L2-resident).
__device__ float g_ker[NCOMBO * KSTRIDE];
// Scratch for global min/max (monotonic-uint encoded floats).
__device__ unsigned g_mm[2];

__device__ __forceinline__ unsigned encf(float f) {
    unsigned u = __float_as_uint(f);
    return (u & 0x80000000u) ? ~u : (u | 0x80000000u);
}
__device__ __forceinline__ float decf(unsigned u) {
    return (u & 0x80000000u) ? __uint_as_float(u ^ 0x80000000u)
                             : __uint_as_float(~u);
}

__global__ void k_init() {
    g_mm[0] = 0xFFFFFFFFu;  // min identity (encoded)
    g_mm[1] = 0u;           // max identity (encoded)
}

// Fill the 3600-entry kernel table. One block per (theta, freq) combo.
__global__ __launch_bounds__(128) void k_fill()
{
    const int combo = blockIdx.x;
    const int t  = combo / 20;
    const int fi = combo % 20;

    // EXACT same FP expressions as the validated direct kernel.
    const float th = (float)t / 180.0f * 3.14159265358979323846f;
    const float f0 = fmaf(0.0015f, (float)fi, 0.025f);
    float st, ct;
    sincosf(th, &st, &ct);
    const float f45 = f0 * (1.0f / 45.0f);

    float* dst = &g_ker[combo * KSTRIDE];
    for (int k = threadIdx.x; k < KSTRIDE; k += 128) {
        const int a = k >> 5;        // kernel row 0..30
        const int b = k & 31;        // kernel col 0..31 (31 = zero pad)
        float w = 0.0f;
        if (b < KS) {
            const float y = (float)(a - PADK);
            const float x = (float)(b - PADK);
            const float yct = y * ct;
            const float yst = y * st;
            const float xt = fmaf(x, ct, yst);
            const float yt = fmaf(-x, st, yct);
            const float ga = fmaf(0.04f, fabsf(yt), 1.0f);
            const float gy = ga * yt;
            const float q  = fmaf(gy, gy, xt * xt);
            const float env = expf(q * (-1.0f / 72.0f));
            const float fl  = fmaf(f45, yt, f0);
            w = env * cosf(6.283185307179586f * fl * xt);
        }
        dst[k] = w;
    }
}

// Convolution: one warp per output pixel, lane l handles kernel column l.
// ker loads: one aligned 128B line per warp-load (fully coalesced, L2-resident).
__global__ __launch_bounds__(256) void k_conv(
    const float* __restrict__ fp,
    const int*   __restrict__ fmap,
    const int*   __restrict__ tmap,
    float* __restrict__ out)
{
    __shared__ float sm[SMR * SMC];
    __shared__ unsigned swmin[PXB], swmax[PXB];

    const int tid  = threadIdx.x;
    const int lane = tid & 31;
    const int w    = tid >> 5;              // warp id = pixel slot 0..7
    const int oy   = blockIdx.y;            // output row
    const int ox0  = blockIdx.x * PXB;      // first output col of block

    // Load input patch rows oy..oy+30, cols ox0..ox0+39 (zero-fill OOB).
    for (int i = tid; i < SMR * SMC; i += 256) {
        const int r = i / SMC, c = i % SMC;
        const int gx = ox0 + c;             // row oy+r is always < 320
        sm[i] = (gx < WW) ? fp[(oy + r) * WW + gx] : 0.0f;
    }
    __syncthreads();

    const int ox = ox0 + w;
    const bool valid = (ox < HOUT);
    const int ci = (oy + PADK) * WW + (ox + PADK);
    const int cis = valid ? ci : (PADK * WW + PADK);
    const int combo = tmap[cis] * 20 + fmap[cis];
    const float* __restrict__ kr = &g_ker[combo * KSTRIDE];

    // lane l accumulates over kernel rows for column b = l (l==31 -> weight 0).
    float acc = 0.0f;
    const float* __restrict__ prow = &sm[w + lane];
    #pragma unroll
    for (int a = 0; a < KS; ++a) {
        const float wv = kr[a * KROW + lane];   // coalesced 128B line
        const float pv = prow[a * SMC];         // conflict-free LDS
        acc = fmaf(pv, wv, acc);
    }
    // Warp reduction across kernel columns.
    #pragma unroll
    for (int off = 16; off > 0; off >>= 1)
        acc += __shfl_down_sync(0xFFFFFFFFu, acc, off);

    if (lane == 0) {
        if (valid) out[ci] = acc;
        swmin[w] = valid ? encf(acc) : 0xFFFFFFFFu;
        swmax[w] = valid ? encf(acc) : 0u;
    }
    __syncthreads();
    if (tid == 0) {
        unsigned m = 0xFFFFFFFFu, M = 0u;
        #pragma unroll
        for (int i = 0; i < PXB; ++i) { m = min(m, swmin[i]); M = max(M, swmax[i]); }
        atomicMin(&g_mm[0], m);
        atomicMax(&g_mm[1], M);
    }
}

__global__ __launch_bounds__(256) void k_border(
    const float* __restrict__ fp, float* __restrict__ out)
{
    __shared__ unsigned swmin[8], swmax[8];
    const int idx = blockIdx.x * 256 + threadIdx.x;
    const int i = idx / WW, j = idx % WW;
    const bool border = (i < PADK) || (i >= PADK + HOUT) ||
                        (j < PADK) || (j >= PADK + HOUT);
    unsigned km = 0xFFFFFFFFu, kM = 0u;
    if (idx < HH * WW && border) {
        float v = fp[idx];
        out[idx] = v;
        km = kM = encf(v);
    }
    km = __reduce_min_sync(0xFFFFFFFFu, km);
    kM = __reduce_max_sync(0xFFFFFFFFu, kM);
    const int lane = threadIdx.x & 31, wid = threadIdx.x >> 5;
    if (lane == 0) { swmin[wid] = km; swmax[wid] = kM; }
    __syncthreads();
    if (threadIdx.x == 0) {
        unsigned m = 0xFFFFFFFFu, M = 0u;
        #pragma unroll
        for (int i2 = 0; i2 < 8; ++i2) { m = min(m, swmin[i2]); M = max(M, swmax[i2]); }
        atomicMin(&g_mm[0], m);
        atomicMax(&g_mm[1], M);
    }
}

__global__ __launch_bounds__(256) void k_thresh(float* __restrict__ out)
{
    const int idx = blockIdx.x * 256 + threadIdx.x;
    if (idx >= HH * WW) return;
    const float mn  = decf(g_mm[0]);
    const float mxv = decf(g_mm[1]) - mn;   // max of (out - min)
    float v = out[idx] - mn;
    float t = (mxv != 0.0f) ? (v / mxv * 100.0f) : v;
    out[idx] = (t > 55.0f) ? 100.0f : 0.0f;
}

extern "C" void kernel_launch(void* const* d_in, const int* in_sizes, int n_in,
                              void* d_out, int out_size)
{
    const float* fp   = (const float*)d_in[0];   // fprint
    const int*   fmap = (const int*)d_in[1];     // freq_map
    const int*   tmap = (const int*)d_in[2];     // theta_map
    float* out = (float*)d_out;

    k_init<<<1, 1>>>();
    k_fill<<<NCOMBO, 128>>>();
    dim3 cgrid((HOUT + PXB - 1) / PXB, HOUT);    // 37 x 289
    k_conv<<<cgrid, 256>>>(fp, fmap, tmap, out);
    k_border<<<(HH * WW + 255) / 256, 256>>>(fp, out);
    k_thresh<<<(HH * WW + 255) / 256, 256>>>(out);
}